// round 11
// baseline (speedup 1.0000x reference)
#include <cuda_runtime.h>
#include <cuda_bf16.h>
#include <math.h>
#include <stdint.h>

#define B_SZ 512
#define T_SZ 256
#define F_SZ 1024
#define KP   3072               // K' = 3*F (tri-concat bf16 split)
#define SPLITK 4
#define KSL  (KP / SPLITK)      // 768 per split slice
#define NSTAGE (KSL / 32)       // 24 stages of 32 bf16
#define SROW 40                 // smem row stride in bf16 (conflict-free)
#define TSPLIT 4
#define TCH (T_SZ / TSPLIT)     // 64 rows per CTA, 8 per warp

// Scratch (allocation-free rule: __device__ globals)
__device__ float  g_part[SPLITK * B_SZ * F_SZ];
__device__ float  g_pacc[TSPLIT * B_SZ * F_SZ];
__device__ float2 g_pmz[TSPLIT * B_SZ];
__device__ __nv_bfloat16 g_actA[B_SZ * KP];   // activation triple (z -> q -> ctxf)
__device__ __nv_bfloat16 g_WqB[F_SZ * KP];
__device__ __nv_bfloat16 g_WkB[F_SZ * KP];    // transposed Wk triple
__device__ __nv_bfloat16 g_WvB[F_SZ * KP];

// ===========================================================================
// bf16 split helpers
// ===========================================================================
__device__ __forceinline__ void split4(float4 v, uint2& hi, uint2& lo) {
    __nv_bfloat16 hx = __float2bfloat16_rn(v.x), hy = __float2bfloat16_rn(v.y);
    __nv_bfloat16 hz = __float2bfloat16_rn(v.z), hw = __float2bfloat16_rn(v.w);
    __nv_bfloat16 lx = __float2bfloat16_rn(v.x - __bfloat162float(hx));
    __nv_bfloat16 ly = __float2bfloat16_rn(v.y - __bfloat162float(hy));
    __nv_bfloat16 lz = __float2bfloat16_rn(v.z - __bfloat162float(hz));
    __nv_bfloat16 lw = __float2bfloat16_rn(v.w - __bfloat162float(hw));
    __nv_bfloat162 h0 = __nv_bfloat162(hx, hy), h1 = __nv_bfloat162(hz, hw);
    __nv_bfloat162 l0 = __nv_bfloat162(lx, ly), l1 = __nv_bfloat162(lz, lw);
    hi.x = *(unsigned*)&h0; hi.y = *(unsigned*)&h1;
    lo.x = *(unsigned*)&l0; lo.y = *(unsigned*)&l1;
}

// Weight conversion, no transpose, B-pattern [hi | hi | lo]. 4 float4/thread.
// grid 256 x 256.
__global__ __launch_bounds__(256) void conv_w_nt(const float* __restrict__ W,
                                                 __nv_bfloat16* __restrict__ out)
{
    const int i0 = blockIdx.x * 1024 + threadIdx.x;
    float4 v[4];
    #pragma unroll
    for (int u = 0; u < 4; u++) v[u] = ((const float4*)W)[i0 + u * 256];
    #pragma unroll
    for (int u = 0; u < 4; u++) {
        int idx = i0 + u * 256;
        int row = idx >> 8, c = (idx & 255) * 4;
        uint2 hi, lo; split4(v[u], hi, lo);
        __nv_bfloat16* base = out + (size_t)row * KP + c;
        *(uint2*)(base)        = hi;
        *(uint2*)(base + 1024) = hi;
        *(uint2*)(base + 2048) = lo;
    }
}

// Wk transpose + convert, B-pattern. grid (32,32), block (32,8).
__global__ void conv_w_t(const float* __restrict__ W, __nv_bfloat16* __restrict__ out)
{
    __shared__ float t[32][33];
    int f0 = blockIdx.x * 32, d0 = blockIdx.y * 32;
    int tx = threadIdx.x, ty = threadIdx.y;
    #pragma unroll
    for (int i = 0; i < 32; i += 8)
        t[ty + i][tx] = W[(size_t)(d0 + ty + i) * F_SZ + f0 + tx];   // t[dd][ff]
    __syncthreads();
    #pragma unroll
    for (int i = 0; i < 32; i += 8) {
        float v = t[tx][ty + i];                   // dd=tx, ff=ty+i
        __nv_bfloat16 hi = __float2bfloat16_rn(v);
        __nv_bfloat16 lo = __float2bfloat16_rn(v - __bfloat162float(hi));
        __nv_bfloat16* base = out + (size_t)(f0 + ty + i) * KP + d0 + tx;
        base[0]    = hi;
        base[1024] = hi;
        base[2048] = lo;
    }
}

// Activation conversion, A-pattern [hi | lo | hi]. 4 float4/thread. grid 128.
__global__ __launch_bounds__(256) void conv_act(const float* __restrict__ X,
                                                __nv_bfloat16* __restrict__ out)
{
    const int i0 = blockIdx.x * 1024 + threadIdx.x;
    float4 v[4];
    #pragma unroll
    for (int u = 0; u < 4; u++) v[u] = ((const float4*)X)[i0 + u * 256];
    #pragma unroll
    for (int u = 0; u < 4; u++) {
        int idx = i0 + u * 256;
        int row = idx >> 8, c = (idx & 255) * 4;
        uint2 hi, lo; split4(v[u], hi, lo);
        __nv_bfloat16* base = out + (size_t)row * KP + c;
        *(uint2*)(base)        = hi;
        *(uint2*)(base + 1024) = lo;
        *(uint2*)(base + 2048) = hi;
    }
}

// Reduce split-K partials + bias -> A-pattern bf16 triple. 4/thread. grid 128.
__global__ __launch_bounds__(256) void reduce_conv(const float* __restrict__ part,
                                                   const float* __restrict__ bias,
                                                   __nv_bfloat16* __restrict__ out)
{
    const int i0 = blockIdx.x * 1024 + threadIdx.x;
    const int Q = B_SZ * F_SZ / 4;
    const float4* p = (const float4*)part;
    float4 a[4], b[4], c4[4], d[4];
    #pragma unroll
    for (int u = 0; u < 4; u++) {
        int idx = i0 + u * 256;
        a[u] = p[idx]; b[u] = p[idx + Q]; c4[u] = p[idx + 2 * Q]; d[u] = p[idx + 3 * Q];
    }
    #pragma unroll
    for (int u = 0; u < 4; u++) {
        int idx = i0 + u * 256;
        float4 bb = ((const float4*)bias)[idx & 255];
        float4 v;
        v.x = (a[u].x + b[u].x) + (c4[u].x + d[u].x) + bb.x;
        v.y = (a[u].y + b[u].y) + (c4[u].y + d[u].y) + bb.y;
        v.z = (a[u].z + b[u].z) + (c4[u].z + d[u].z) + bb.z;
        v.w = (a[u].w + b[u].w) + (c4[u].w + d[u].w) + bb.w;
        int row = idx >> 8, c = (idx & 255) * 4;
        uint2 hi, lo; split4(v, hi, lo);
        __nv_bfloat16* base = out + (size_t)row * KP + c;
        *(uint2*)(base)        = hi;
        *(uint2*)(base + 1024) = lo;
        *(uint2*)(base + 2048) = hi;
    }
}

// ===========================================================================
// bf16 HMMA GEMM (UNCHANGED from R10 win). Grid (8, 4, SPLITK).
// ===========================================================================
__device__ __forceinline__ void mma16816(float* c, const uint32_t* a, const uint32_t* b) {
    asm volatile(
        "mma.sync.aligned.m16n8k16.row.col.f32.bf16.bf16.f32 "
        "{%0,%1,%2,%3}, {%4,%5,%6,%7}, {%8,%9}, {%0,%1,%2,%3};"
        : "+f"(c[0]), "+f"(c[1]), "+f"(c[2]), "+f"(c[3])
        : "r"(a[0]), "r"(a[1]), "r"(a[2]), "r"(a[3]), "r"(b[0]), "r"(b[1]));
}

__global__ __launch_bounds__(256) void mma_gemm(const __nv_bfloat16* __restrict__ Aq,
                                                const __nv_bfloat16* __restrict__ Bq,
                                                float* __restrict__ Cpart)
{
    __shared__ __align__(16) __nv_bfloat16 sA[2][128 * SROW];
    __shared__ __align__(16) __nv_bfloat16 sB[2][128 * SROW];

    const int bn = blockIdx.x * 128;
    const int bm = blockIdx.y * 128;
    const int s  = blockIdx.z;
    const int k0 = s * KSL;
    const int tid = threadIdx.x;
    const int wid = tid >> 5;
    const int l = tid & 31;
    const int wm = wid & 1;
    const int wn = wid >> 1;
    const int lq = l >> 2;
    const int lr = l & 3;

    const int row0 = tid >> 2,           kc0 = (tid & 3) * 8;
    const int row1 = (tid + 256) >> 2,   kc1 = (tid & 3) * 8;

    const __nv_bfloat16* Ag0 = Aq + (size_t)(bm + row0) * KP + k0 + kc0;
    const __nv_bfloat16* Ag1 = Aq + (size_t)(bm + row1) * KP + k0 + kc1;
    const __nv_bfloat16* Bg0 = Bq + (size_t)(bn + row0) * KP + k0 + kc0;
    const __nv_bfloat16* Bg1 = Bq + (size_t)(bn + row1) * KP + k0 + kc1;

    const int sa0 = row0 * SROW + kc0, sa1 = row1 * SROW + kc1;

    float acc[4][4][4];
    #pragma unroll
    for (int i = 0; i < 4; i++)
        #pragma unroll
        for (int j = 0; j < 4; j++)
            #pragma unroll
            for (int r = 0; r < 4; r++) acc[i][j][r] = 0.f;

    {
        uint4 a0 = *(const uint4*)Ag0, a1 = *(const uint4*)Ag1;
        uint4 b0 = *(const uint4*)Bg0, b1 = *(const uint4*)Bg1;
        *(uint4*)&sA[0][sa0] = a0; *(uint4*)&sA[0][sa1] = a1;
        *(uint4*)&sB[0][sa0] = b0; *(uint4*)&sB[0][sa1] = b1;
    }
    __syncthreads();

    int buf = 0;
    for (int st = 0; st < NSTAGE; st++) {
        uint4 pa0, pa1, pb0, pb1;
        if (st + 1 < NSTAGE) {
            pa0 = *(const uint4*)(Ag0 + (st + 1) * 32);
            pa1 = *(const uint4*)(Ag1 + (st + 1) * 32);
            pb0 = *(const uint4*)(Bg0 + (st + 1) * 32);
            pb1 = *(const uint4*)(Bg1 + (st + 1) * 32);
        }

        #pragma unroll
        for (int ks = 0; ks < 2; ks++) {
            const int kc = ks * 16 + lr * 2;
            uint32_t af[4][4];
            #pragma unroll
            for (int i = 0; i < 4; i++) {
                const __nv_bfloat16* base = &sA[buf][(wm * 64 + i * 16 + lq) * SROW + kc];
                af[i][0] = *(const uint32_t*)(base);
                af[i][1] = *(const uint32_t*)(base + 8 * SROW);
                af[i][2] = *(const uint32_t*)(base + 8);
                af[i][3] = *(const uint32_t*)(base + 8 * SROW + 8);
            }
            uint32_t bfr[4][2];
            #pragma unroll
            for (int j = 0; j < 4; j++) {
                const __nv_bfloat16* base = &sB[buf][(wn * 32 + j * 8 + lq) * SROW + kc];
                bfr[j][0] = *(const uint32_t*)(base);
                bfr[j][1] = *(const uint32_t*)(base + 8);
            }
            #pragma unroll
            for (int i = 0; i < 4; i++)
                #pragma unroll
                for (int j = 0; j < 4; j++)
                    mma16816(acc[i][j], af[i], bfr[j]);
        }

        if (st + 1 < NSTAGE) {
            int nb = buf ^ 1;
            *(uint4*)&sA[nb][sa0] = pa0; *(uint4*)&sA[nb][sa1] = pa1;
            *(uint4*)&sB[nb][sa0] = pb0; *(uint4*)&sB[nb][sa1] = pb1;
            __syncthreads();
            buf = nb;
        }
    }

    float* Cp = Cpart + (size_t)s * (B_SZ * F_SZ);
    #pragma unroll
    for (int i = 0; i < 4; i++) {
        #pragma unroll
        for (int j = 0; j < 4; j++) {
            int row = bm + wm * 64 + i * 16 + lq;
            int col = bn + wn * 32 + j * 8 + lr * 2;
            *(float2*)(Cp + (size_t)row * F_SZ + col) =
                make_float2(acc[i][j][0], acc[i][j][1]);
            *(float2*)(Cp + (size_t)(row + 8) * F_SZ + col) =
                make_float2(acc[i][j][2], acc[i][j][3]);
        }
    }
}

// ---------------------------------------------------------------------------
// Reduce SPLITK partials (+ bias) -> fp32 out. 4 float4/thread, grid 128.
// ---------------------------------------------------------------------------
__global__ __launch_bounds__(256) void reduce_k(const float* __restrict__ part,
                                                const float* __restrict__ bias,
                                                float* __restrict__ out)
{
    const int base = blockIdx.x * 1024 + threadIdx.x;
    const int Q = B_SZ * F_SZ / 4;
    const float4* p = (const float4*)part;
    float4 a[4], b[4], c[4], d[4];
    #pragma unroll
    for (int u = 0; u < 4; u++) {
        int idx = base + u * 256;
        a[u] = p[idx]; b[u] = p[idx + Q]; c[u] = p[idx + 2 * Q]; d[u] = p[idx + 3 * Q];
    }
    #pragma unroll
    for (int u = 0; u < 4; u++) {
        int idx = base + u * 256;
        float4 bb = ((const float4*)bias)[idx & 255];
        float4 o;
        o.x = (a[u].x + b[u].x) + (c[u].x + d[u].x) + bb.x;
        o.y = (a[u].y + b[u].y) + (c[u].y + d[u].y) + bb.y;
        o.z = (a[u].z + b[u].z) + (c[u].z + d[u].z) + bb.z;
        o.w = (a[u].w + b[u].w) + (c[u].w + d[u].w) + bb.w;
        ((float4*)out)[idx] = o;
    }
}

// ---------------------------------------------------------------------------
// Attention partial, WARP-PRIVATE: grid (B, TSPLIT). Warp w owns 8 consecutive
// T-rows; lane holds a 32-float column fragment. Score = register dot +
// shfl_xor butterfly. Online softmax is warp-local with deferred rescale.
// ZERO __syncthreads in the T-loop; one smem flash-merge at the end.
// ---------------------------------------------------------------------------
__global__ __launch_bounds__(256, 2) void attn_part(const float* __restrict__ x,
                                                    const float* __restrict__ qkpart,
                                                    float* __restrict__ pacc,
                                                    float2* __restrict__ pmz)
{
    const int b = blockIdx.x;
    const int h = blockIdx.y;
    const int tid = threadIdx.x;
    const int w = tid >> 5;
    const int l = tid & 31;

    __shared__ float4 qk4s[256];        // 4 KB
    __shared__ float4 wacc[8][256];     // 32 KB
    __shared__ float  wm[8], wz[8];

    // qk[b,:] = sum of 4 split-K partials
    {
        const int Q = B_SZ * F_SZ / 4;
        const int idx = b * 256 + tid;
        const float4* p = (const float4*)qkpart;
        float4 a = p[idx], bb = p[idx + Q], c = p[idx + 2 * Q], d = p[idx + 3 * Q];
        qk4s[tid] = make_float4((a.x + bb.x) + (c.x + d.x),
                                (a.y + bb.y) + (c.y + d.y),
                                (a.z + bb.z) + (c.z + d.z),
                                (a.w + bb.w) + (c.w + d.w));
    }
    __syncthreads();

    const float4* x4 = (const float4*)(x + (size_t)b * T_SZ * F_SZ
                                         + (size_t)h * TCH * F_SZ);
    const int row0 = w * 8;             // this warp's first row

    float4 cur[8], nxt[8];
    #pragma unroll
    for (int j = 0; j < 8; j++) cur[j] = x4[(size_t)row0 * 256 + l + 32 * j];

    float m = -INFINITY, Z = 0.0f;
    float4 acc[8];
    #pragma unroll
    for (int j = 0; j < 8; j++) acc[j] = make_float4(0.f, 0.f, 0.f, 0.f);

    #pragma unroll
    for (int r = 0; r < 8; r++) {
        if (r < 7) {                    // next row's LDGs in flight over score
            #pragma unroll
            for (int j = 0; j < 8; j++)
                nxt[j] = x4[(size_t)(row0 + r + 1) * 256 + l + 32 * j];
        }

        float p = 0.f;
        #pragma unroll
        for (int j = 0; j < 8; j++) {
            float4 xv = cur[j], qv = qk4s[l + 32 * j];
            p += xv.x * qv.x + xv.y * qv.y + xv.z * qv.z + xv.w * qv.w;
        }
        #pragma unroll
        for (int off = 16; off; off >>= 1)
            p += __shfl_xor_sync(0xffffffffu, p, off);

        if (p > m) {                    // deferred rescale (uniform across warp)
            float scale = __expf(m - p);   // first row: exp(-inf)=0
            Z *= scale;
            #pragma unroll
            for (int j = 0; j < 8; j++) {
                acc[j].x *= scale; acc[j].y *= scale;
                acc[j].z *= scale; acc[j].w *= scale;
            }
            m = p;
        }
        float wt = __expf(p - m);
        Z += wt;
        #pragma unroll
        for (int j = 0; j < 8; j++) {
            acc[j].x += wt * cur[j].x; acc[j].y += wt * cur[j].y;
            acc[j].z += wt * cur[j].z; acc[j].w += wt * cur[j].w;
        }

        if (r < 7) {
            #pragma unroll
            for (int j = 0; j < 8; j++) cur[j] = nxt[j];
        }
    }

    // flash-merge the 8 warps
    if (l == 0) { wm[w] = m; wz[w] = Z; }
    #pragma unroll
    for (int j = 0; j < 8; j++) wacc[w][l + 32 * j] = acc[j];
    __syncthreads();

    float M = wm[0];
    #pragma unroll
    for (int i = 1; i < 8; i++) M = fmaxf(M, wm[i]);
    float Zt = 0.f;
    float sc[8];
    #pragma unroll
    for (int i = 0; i < 8; i++) { sc[i] = __expf(wm[i] - M); Zt += wz[i] * sc[i]; }

    float4 o = make_float4(0.f, 0.f, 0.f, 0.f);
    #pragma unroll
    for (int i = 0; i < 8; i++) {
        float4 a = wacc[i][tid];
        o.x += sc[i] * a.x; o.y += sc[i] * a.y;
        o.z += sc[i] * a.z; o.w += sc[i] * a.w;
    }
    ((float4*)pacc)[(size_t)(b * TSPLIT + h) * 256 + tid] = o;
    if (tid == 0) pmz[b * TSPLIT + h] = make_float2(M, Zt);
}

// ---------------------------------------------------------------------------
// Combine T-chunks, normalize, convert to bf16 A-pattern triple for GEMM3.
// ---------------------------------------------------------------------------
__global__ __launch_bounds__(256) void attn_combine_conv(const float* __restrict__ pacc,
                                                         const float2* __restrict__ pmz,
                                                         __nv_bfloat16* __restrict__ out)
{
    const int b = blockIdx.x;
    const int tid = threadIdx.x;

    float2 mz[TSPLIT];
    #pragma unroll
    for (int i = 0; i < TSPLIT; i++) mz[i] = pmz[TSPLIT * b + i];
    float m = mz[0].x;
    #pragma unroll
    for (int i = 1; i < TSPLIT; i++) m = fmaxf(m, mz[i].x);
    float sc[TSPLIT], Z = 0.f;
    #pragma unroll
    for (int i = 0; i < TSPLIT; i++) { sc[i] = __expf(mz[i].x - m); Z += mz[i].y * sc[i]; }
    float inv = 1.0f / Z;

    float4 o = make_float4(0.f, 0.f, 0.f, 0.f);
    #pragma unroll
    for (int i = 0; i < TSPLIT; i++) {
        float4 a = ((const float4*)pacc)[(size_t)(TSPLIT * b + i) * 256 + tid];
        o.x += a.x * sc[i]; o.y += a.y * sc[i];
        o.z += a.z * sc[i]; o.w += a.w * sc[i];
    }
    o.x *= inv; o.y *= inv; o.z *= inv; o.w *= inv;

    uint2 hi, lo; split4(o, hi, lo);
    __nv_bfloat16* base = out + (size_t)b * KP + tid * 4;
    *(uint2*)(base)        = hi;
    *(uint2*)(base + 1024) = lo;
    *(uint2*)(base + 2048) = hi;
}

// ---------------------------------------------------------------------------
extern "C" void kernel_launch(void* const* d_in, const int* in_sizes, int n_in,
                              void* d_out, int out_size)
{
    const float* z  = (const float*)d_in[0];   // [B,F]
    const float* x  = (const float*)d_in[1];   // [B,T,F]
    const float* Wq = (const float*)d_in[2];   // [D,F]
    const float* Wk = (const float*)d_in[3];   // [D,F]
    const float* Wv = (const float*)d_in[4];   // [D,F]
    const float* bq = (const float*)d_in[5];   // [D]
    // d_in[6] = bk: softmax-invariant -> dropped
    const float* bv = (const float*)d_in[7];   // [D]
    float* out = (float*)d_out;                // [B,D]

    float *part, *pacc;
    float2* pmz;
    __nv_bfloat16 *actA, *WqB, *WkB, *WvB;
    cudaGetSymbolAddress((void**)&part, g_part);
    cudaGetSymbolAddress((void**)&pacc, g_pacc);
    cudaGetSymbolAddress((void**)&pmz,  g_pmz);
    cudaGetSymbolAddress((void**)&actA, g_actA);
    cudaGetSymbolAddress((void**)&WqB,  g_WqB);
    cudaGetSymbolAddress((void**)&WkB,  g_WkB);
    cudaGetSymbolAddress((void**)&WvB,  g_WvB);

    dim3 mgrid(8, 4, SPLITK);   // 128 CTAs per GEMM

    // conversions
    conv_w_nt<<<256, 256>>>(Wq, WqB);
    conv_w_t<<<dim3(32, 32), dim3(32, 8)>>>(Wk, WkB);
    conv_w_nt<<<256, 256>>>(Wv, WvB);
    conv_act<<<128, 256>>>(z, actA);

    // 1. q = z @ Wq^T + bq
    mma_gemm<<<mgrid, 256>>>(actA, WqB, part);
    reduce_conv<<<128, 256>>>(part, bq, actA);
    // 2. qk = q @ Wk  (partials consumed directly by attn_part)
    mma_gemm<<<mgrid, 256>>>(actA, WkB, part);
    // 3. fused scores + softmax + weighted-input accumulation
    attn_part<<<dim3(B_SZ, TSPLIT), 256>>>(x, part, pacc, pmz);
    attn_combine_conv<<<B_SZ, 256>>>(pacc, pmz, actA);
    // 4. out = ctxf @ Wv^T + bv
    mma_gemm<<<mgrid, 256>>>(actA, WvB, part);
    reduce_k<<<128, 256>>>(part, bv, out);
}

// round 14
// speedup vs baseline: 1.0836x; 1.0836x over previous
#include <cuda_runtime.h>
#include <cuda_bf16.h>
#include <math.h>
#include <stdint.h>

#define B_SZ 512
#define T_SZ 256
#define F_SZ 1024
#define KP   3072               // K' = 3*F (tri-concat bf16 split)
#define SPLITK 4
#define KSL  (KP / SPLITK)      // 768 per split slice
#define NSTAGE (KSL / 32)       // 24 stages of 32 bf16
#define SROW 40                 // smem row stride in bf16 (conflict-free)
#define TSPLIT 4
#define TCH (T_SZ / TSPLIT)     // 64
#define NIT (TCH / 8)           // 8

// Scratch (allocation-free rule: __device__ globals)
__device__ float  g_part[SPLITK * B_SZ * F_SZ];
__device__ float  g_pacc[TSPLIT * B_SZ * F_SZ];
__device__ float2 g_pmz[TSPLIT * B_SZ];
__device__ __nv_bfloat16 g_actA[B_SZ * KP];   // activation triple (z -> q -> ctxf)
__device__ __nv_bfloat16 g_WqB[F_SZ * KP];
__device__ __nv_bfloat16 g_WkB[F_SZ * KP];    // transposed Wk triple
__device__ __nv_bfloat16 g_WvB[F_SZ * KP];

// ===========================================================================
// bf16 split helpers
// ===========================================================================
__device__ __forceinline__ void split4(float4 v, uint2& hi, uint2& lo) {
    __nv_bfloat16 hx = __float2bfloat16_rn(v.x), hy = __float2bfloat16_rn(v.y);
    __nv_bfloat16 hz = __float2bfloat16_rn(v.z), hw = __float2bfloat16_rn(v.w);
    __nv_bfloat16 lx = __float2bfloat16_rn(v.x - __bfloat162float(hx));
    __nv_bfloat16 ly = __float2bfloat16_rn(v.y - __bfloat162float(hy));
    __nv_bfloat16 lz = __float2bfloat16_rn(v.z - __bfloat162float(hz));
    __nv_bfloat16 lw = __float2bfloat16_rn(v.w - __bfloat162float(hw));
    __nv_bfloat162 h0 = __nv_bfloat162(hx, hy), h1 = __nv_bfloat162(hz, hw);
    __nv_bfloat162 l0 = __nv_bfloat162(lx, ly), l1 = __nv_bfloat162(lz, lw);
    hi.x = *(unsigned*)&h0; hi.y = *(unsigned*)&h1;
    lo.x = *(unsigned*)&l0; lo.y = *(unsigned*)&l1;
}

// ===========================================================================
// ONE merged conversion kernel (4 independent jobs, block-range dispatch):
//   blocks [0,256)    : Wq  -> B-pattern [hi|hi|lo], no transpose
//   blocks [256,512)  : Wv  -> B-pattern, no transpose
//   blocks [512,640)  : z   -> A-pattern [hi|lo|hi]
//   blocks [640,1664) : Wk  -> transpose + B-pattern
// ===========================================================================
__global__ __launch_bounds__(256) void conv_all(const float* __restrict__ Wq,
                                                const float* __restrict__ Wv,
                                                const float* __restrict__ z,
                                                const float* __restrict__ Wk,
                                                __nv_bfloat16* __restrict__ WqB,
                                                __nv_bfloat16* __restrict__ WvB,
                                                __nv_bfloat16* __restrict__ actA,
                                                __nv_bfloat16* __restrict__ WkB)
{
    const int bid = blockIdx.x;
    const int t = threadIdx.x;

    if (bid < 512) {                      // Wq or Wv, B-pattern
        const float* W = (bid < 256) ? Wq : Wv;
        __nv_bfloat16* out = (bid < 256) ? WqB : WvB;
        const int i0 = (bid & 255) * 1024 + t;
        #pragma unroll
        for (int u = 0; u < 4; u++) {
            int idx = i0 + u * 256;
            float4 v = ((const float4*)W)[idx];
            int row = idx >> 8, c = (idx & 255) * 4;
            uint2 hi, lo; split4(v, hi, lo);
            __nv_bfloat16* base = out + (size_t)row * KP + c;
            *(uint2*)(base)        = hi;
            *(uint2*)(base + 1024) = hi;
            *(uint2*)(base + 2048) = lo;
        }
    } else if (bid < 640) {               // z, A-pattern
        const int i0 = (bid - 512) * 1024 + t;
        #pragma unroll
        for (int u = 0; u < 4; u++) {
            int idx = i0 + u * 256;
            float4 v = ((const float4*)z)[idx];
            int row = idx >> 8, c = (idx & 255) * 4;
            uint2 hi, lo; split4(v, hi, lo);
            __nv_bfloat16* base = actA + (size_t)row * KP + c;
            *(uint2*)(base)        = hi;
            *(uint2*)(base + 1024) = lo;
            *(uint2*)(base + 2048) = hi;
        }
    } else {                              // Wk transpose + B-pattern
        __shared__ float tl[32][33];
        const int r = bid - 640;          // 0..1023
        const int f0 = (r & 31) * 32, d0 = (r >> 5) * 32;
        const int tx = t & 31, ty = t >> 5;    // 32 x 8
        #pragma unroll
        for (int i = 0; i < 32; i += 8)
            tl[ty + i][tx] = Wk[(size_t)(d0 + ty + i) * F_SZ + f0 + tx];
        __syncthreads();
        #pragma unroll
        for (int i = 0; i < 32; i += 8) {
            float v = tl[tx][ty + i];
            __nv_bfloat16 hi = __float2bfloat16_rn(v);
            __nv_bfloat16 lo = __float2bfloat16_rn(v - __bfloat162float(hi));
            __nv_bfloat16* base = WkB + (size_t)(f0 + ty + i) * KP + d0 + tx;
            base[0]    = hi;
            base[1024] = hi;
            base[2048] = lo;
        }
    }
}

// Reduce split-K partials + bias -> A-pattern bf16 triple. 4/thread. grid 128.
__global__ __launch_bounds__(256) void reduce_conv(const float* __restrict__ part,
                                                   const float* __restrict__ bias,
                                                   __nv_bfloat16* __restrict__ out)
{
    const int i0 = blockIdx.x * 1024 + threadIdx.x;
    const int Q = B_SZ * F_SZ / 4;
    const float4* p = (const float4*)part;
    float4 a[4], b[4], c4[4], d[4];
    #pragma unroll
    for (int u = 0; u < 4; u++) {
        int idx = i0 + u * 256;
        a[u] = p[idx]; b[u] = p[idx + Q]; c4[u] = p[idx + 2 * Q]; d[u] = p[idx + 3 * Q];
    }
    #pragma unroll
    for (int u = 0; u < 4; u++) {
        int idx = i0 + u * 256;
        float4 bb = ((const float4*)bias)[idx & 255];
        float4 v;
        v.x = (a[u].x + b[u].x) + (c4[u].x + d[u].x) + bb.x;
        v.y = (a[u].y + b[u].y) + (c4[u].y + d[u].y) + bb.y;
        v.z = (a[u].z + b[u].z) + (c4[u].z + d[u].z) + bb.z;
        v.w = (a[u].w + b[u].w) + (c4[u].w + d[u].w) + bb.w;
        int row = idx >> 8, c = (idx & 255) * 4;
        uint2 hi, lo; split4(v, hi, lo);
        __nv_bfloat16* base = out + (size_t)row * KP + c;
        *(uint2*)(base)        = hi;
        *(uint2*)(base + 1024) = lo;
        *(uint2*)(base + 2048) = hi;
    }
}

// ===========================================================================
// bf16 HMMA GEMM (UNCHANGED from R10 win). Grid (8, 4, SPLITK).
// ===========================================================================
__device__ __forceinline__ void mma16816(float* c, const uint32_t* a, const uint32_t* b) {
    asm volatile(
        "mma.sync.aligned.m16n8k16.row.col.f32.bf16.bf16.f32 "
        "{%0,%1,%2,%3}, {%4,%5,%6,%7}, {%8,%9}, {%0,%1,%2,%3};"
        : "+f"(c[0]), "+f"(c[1]), "+f"(c[2]), "+f"(c[3])
        : "r"(a[0]), "r"(a[1]), "r"(a[2]), "r"(a[3]), "r"(b[0]), "r"(b[1]));
}

__global__ __launch_bounds__(256) void mma_gemm(const __nv_bfloat16* __restrict__ Aq,
                                                const __nv_bfloat16* __restrict__ Bq,
                                                float* __restrict__ Cpart)
{
    __shared__ __align__(16) __nv_bfloat16 sA[2][128 * SROW];
    __shared__ __align__(16) __nv_bfloat16 sB[2][128 * SROW];

    const int bn = blockIdx.x * 128;
    const int bm = blockIdx.y * 128;
    const int s  = blockIdx.z;
    const int k0 = s * KSL;
    const int tid = threadIdx.x;
    const int wid = tid >> 5;
    const int l = tid & 31;
    const int wm = wid & 1;
    const int wn = wid >> 1;
    const int lq = l >> 2;
    const int lr = l & 3;

    const int row0 = tid >> 2,           kc0 = (tid & 3) * 8;
    const int row1 = (tid + 256) >> 2,   kc1 = (tid & 3) * 8;

    const __nv_bfloat16* Ag0 = Aq + (size_t)(bm + row0) * KP + k0 + kc0;
    const __nv_bfloat16* Ag1 = Aq + (size_t)(bm + row1) * KP + k0 + kc1;
    const __nv_bfloat16* Bg0 = Bq + (size_t)(bn + row0) * KP + k0 + kc0;
    const __nv_bfloat16* Bg1 = Bq + (size_t)(bn + row1) * KP + k0 + kc1;

    const int sa0 = row0 * SROW + kc0, sa1 = row1 * SROW + kc1;

    float acc[4][4][4];
    #pragma unroll
    for (int i = 0; i < 4; i++)
        #pragma unroll
        for (int j = 0; j < 4; j++)
            #pragma unroll
            for (int r = 0; r < 4; r++) acc[i][j][r] = 0.f;

    {
        uint4 a0 = *(const uint4*)Ag0, a1 = *(const uint4*)Ag1;
        uint4 b0 = *(const uint4*)Bg0, b1 = *(const uint4*)Bg1;
        *(uint4*)&sA[0][sa0] = a0; *(uint4*)&sA[0][sa1] = a1;
        *(uint4*)&sB[0][sa0] = b0; *(uint4*)&sB[0][sa1] = b1;
    }
    __syncthreads();

    int buf = 0;
    for (int st = 0; st < NSTAGE; st++) {
        uint4 pa0, pa1, pb0, pb1;
        if (st + 1 < NSTAGE) {
            pa0 = *(const uint4*)(Ag0 + (st + 1) * 32);
            pa1 = *(const uint4*)(Ag1 + (st + 1) * 32);
            pb0 = *(const uint4*)(Bg0 + (st + 1) * 32);
            pb1 = *(const uint4*)(Bg1 + (st + 1) * 32);
        }

        #pragma unroll
        for (int ks = 0; ks < 2; ks++) {
            const int kc = ks * 16 + lr * 2;
            uint32_t af[4][4];
            #pragma unroll
            for (int i = 0; i < 4; i++) {
                const __nv_bfloat16* base = &sA[buf][(wm * 64 + i * 16 + lq) * SROW + kc];
                af[i][0] = *(const uint32_t*)(base);
                af[i][1] = *(const uint32_t*)(base + 8 * SROW);
                af[i][2] = *(const uint32_t*)(base + 8);
                af[i][3] = *(const uint32_t*)(base + 8 * SROW + 8);
            }
            uint32_t bfr[4][2];
            #pragma unroll
            for (int j = 0; j < 4; j++) {
                const __nv_bfloat16* base = &sB[buf][(wn * 32 + j * 8 + lq) * SROW + kc];
                bfr[j][0] = *(const uint32_t*)(base);
                bfr[j][1] = *(const uint32_t*)(base + 8);
            }
            #pragma unroll
            for (int i = 0; i < 4; i++)
                #pragma unroll
                for (int j = 0; j < 4; j++)
                    mma16816(acc[i][j], af[i], bfr[j]);
        }

        if (st + 1 < NSTAGE) {
            int nb = buf ^ 1;
            *(uint4*)&sA[nb][sa0] = pa0; *(uint4*)&sA[nb][sa1] = pa1;
            *(uint4*)&sB[nb][sa0] = pb0; *(uint4*)&sB[nb][sa1] = pb1;
            __syncthreads();
            buf = nb;
        }
    }

    float* Cp = Cpart + (size_t)s * (B_SZ * F_SZ);
    #pragma unroll
    for (int i = 0; i < 4; i++) {
        #pragma unroll
        for (int j = 0; j < 4; j++) {
            int row = bm + wm * 64 + i * 16 + lq;
            int col = bn + wn * 32 + j * 8 + lr * 2;
            *(float2*)(Cp + (size_t)row * F_SZ + col) =
                make_float2(acc[i][j][0], acc[i][j][1]);
            *(float2*)(Cp + (size_t)(row + 8) * F_SZ + col) =
                make_float2(acc[i][j][2], acc[i][j][3]);
        }
    }
}

// ---------------------------------------------------------------------------
// Reduce SPLITK partials (+ bias) -> fp32 out. 4 float4/thread, grid 128.
// ---------------------------------------------------------------------------
__global__ __launch_bounds__(256) void reduce_k(const float* __restrict__ part,
                                                const float* __restrict__ bias,
                                                float* __restrict__ out)
{
    const int base = blockIdx.x * 1024 + threadIdx.x;
    const int Q = B_SZ * F_SZ / 4;
    const float4* p = (const float4*)part;
    float4 a[4], b[4], c[4], d[4];
    #pragma unroll
    for (int u = 0; u < 4; u++) {
        int idx = base + u * 256;
        a[u] = p[idx]; b[u] = p[idx + Q]; c[u] = p[idx + 2 * Q]; d[u] = p[idx + 3 * Q];
    }
    #pragma unroll
    for (int u = 0; u < 4; u++) {
        int idx = base + u * 256;
        float4 bb = ((const float4*)bias)[idx & 255];
        float4 o;
        o.x = (a[u].x + b[u].x) + (c[u].x + d[u].x) + bb.x;
        o.y = (a[u].y + b[u].y) + (c[u].y + d[u].y) + bb.y;
        o.z = (a[u].z + b[u].z) + (c[u].z + d[u].z) + bb.z;
        o.w = (a[u].w + b[u].w) + (c[u].w + d[u].w) + bb.w;
        ((float4*)out)[idx] = o;
    }
}

// ---------------------------------------------------------------------------
// Attention partial (R10 version + L2 prefetch of tile t+2). grid (B, TSPLIT).
// ---------------------------------------------------------------------------
__global__ __launch_bounds__(256, 2) void attn_part(const float* __restrict__ x,
                                                    const float* __restrict__ qkpart,
                                                    float* __restrict__ pacc,
                                                    float2* __restrict__ pmz)
{
    const int b = blockIdx.x;
    const int h = blockIdx.y;
    const int tid = threadIdx.x;
    const int w = tid >> 5;
    const int l = tid & 31;

    __shared__ float red[8][256];
    __shared__ float s_tile[8];

    float4 qk;
    {
        const int Q = B_SZ * F_SZ / 4;
        const int idx = b * 256 + tid;
        const float4* p = (const float4*)qkpart;
        float4 a = p[idx], bb = p[idx + Q], c = p[idx + 2 * Q], d = p[idx + 3 * Q];
        qk = make_float4((a.x + bb.x) + (c.x + d.x),
                         (a.y + bb.y) + (c.y + d.y),
                         (a.z + bb.z) + (c.z + d.z),
                         (a.w + bb.w) + (c.w + d.w));
    }

    const float4* x4 = (const float4*)(x + (size_t)b * T_SZ * F_SZ
                                         + (size_t)h * TCH * F_SZ);
    float4 cur[8], nxt[8];
    #pragma unroll
    for (int i = 0; i < 8; i++) cur[i] = x4[(size_t)i * 256 + tid];
    #pragma unroll
    for (int i = 0; i < 8; i++)   // L2 prefetch of tile 1
        asm volatile("prefetch.global.L2 [%0];"
                     :: "l"(x4 + (size_t)(8 + i) * 256 + tid));

    float m = -INFINITY, Z = 0.0f;
    float4 acc = make_float4(0.f, 0.f, 0.f, 0.f);

    #pragma unroll
    for (int it = 0; it < NIT; it++) {
        if (it + 1 < NIT) {
            #pragma unroll
            for (int i = 0; i < 8; i++)
                nxt[i] = x4[(size_t)((it + 1) * 8 + i) * 256 + tid];
        }
        if (it + 2 < NIT) {           // DRAM->L2 prefetch two tiles ahead
            #pragma unroll
            for (int i = 0; i < 8; i++)
                asm volatile("prefetch.global.L2 [%0];"
                             :: "l"(x4 + (size_t)((it + 2) * 8 + i) * 256 + tid));
        }

        #pragma unroll
        for (int i = 0; i < 8; i++) {
            float4 xv = cur[i];
            red[i][tid] = xv.x * qk.x + xv.y * qk.y + xv.z * qk.z + xv.w * qk.w;
        }
        __syncthreads();
        {
            float s = 0.f;
            #pragma unroll
            for (int j = 0; j < 8; j++) s += red[w][l + 32 * j];
            #pragma unroll
            for (int off = 16; off; off >>= 1)
                s += __shfl_down_sync(0xffffffffu, s, off);
            if (l == 0) s_tile[w] = s;
        }
        __syncthreads();

        float tm = s_tile[0];
        #pragma unroll
        for (int t = 1; t < 8; t++) tm = fmaxf(tm, s_tile[t]);
        float m_new = fmaxf(m, tm);
        float scale = __expf(m - m_new);
        Z *= scale;
        acc.x *= scale; acc.y *= scale; acc.z *= scale; acc.w *= scale;
        #pragma unroll
        for (int t = 0; t < 8; t++) {
            float wt = __expf(s_tile[t] - m_new);
            Z += wt;
            float4 xv = cur[t];
            acc.x += wt * xv.x; acc.y += wt * xv.y;
            acc.z += wt * xv.z; acc.w += wt * xv.w;
        }
        m = m_new;
        if (it + 1 < NIT) {
            #pragma unroll
            for (int i = 0; i < 8; i++) cur[i] = nxt[i];
        }
    }

    ((float4*)pacc)[(size_t)(b * TSPLIT + h) * 256 + tid] = acc;
    if (tid == 0) pmz[b * TSPLIT + h] = make_float2(m, Z);
}

// ---------------------------------------------------------------------------
// Combine T-chunks, normalize, convert to bf16 A-pattern triple for GEMM3.
// ---------------------------------------------------------------------------
__global__ __launch_bounds__(256) void attn_combine_conv(const float* __restrict__ pacc,
                                                         const float2* __restrict__ pmz,
                                                         __nv_bfloat16* __restrict__ out)
{
    const int b = blockIdx.x;
    const int tid = threadIdx.x;

    float2 mz[TSPLIT];
    #pragma unroll
    for (int i = 0; i < TSPLIT; i++) mz[i] = pmz[TSPLIT * b + i];
    float m = mz[0].x;
    #pragma unroll
    for (int i = 1; i < TSPLIT; i++) m = fmaxf(m, mz[i].x);
    float sc[TSPLIT], Z = 0.f;
    #pragma unroll
    for (int i = 0; i < TSPLIT; i++) { sc[i] = __expf(mz[i].x - m); Z += mz[i].y * sc[i]; }
    float inv = 1.0f / Z;

    float4 o = make_float4(0.f, 0.f, 0.f, 0.f);
    #pragma unroll
    for (int i = 0; i < TSPLIT; i++) {
        float4 a = ((const float4*)pacc)[(size_t)(TSPLIT * b + i) * 256 + tid];
        o.x += a.x * sc[i]; o.y += a.y * sc[i];
        o.z += a.z * sc[i]; o.w += a.w * sc[i];
    }
    o.x *= inv; o.y *= inv; o.z *= inv; o.w *= inv;

    uint2 hi, lo; split4(o, hi, lo);
    __nv_bfloat16* base = out + (size_t)b * KP + tid * 4;
    *(uint2*)(base)        = hi;
    *(uint2*)(base + 1024) = lo;
    *(uint2*)(base + 2048) = hi;
}

// ---------------------------------------------------------------------------
extern "C" void kernel_launch(void* const* d_in, const int* in_sizes, int n_in,
                              void* d_out, int out_size)
{
    const float* z  = (const float*)d_in[0];   // [B,F]
    const float* x  = (const float*)d_in[1];   // [B,T,F]
    const float* Wq = (const float*)d_in[2];   // [D,F]
    const float* Wk = (const float*)d_in[3];   // [D,F]
    const float* Wv = (const float*)d_in[4];   // [D,F]
    const float* bq = (const float*)d_in[5];   // [D]
    // d_in[6] = bk: softmax-invariant -> dropped
    const float* bv = (const float*)d_in[7];   // [D]
    float* out = (float*)d_out;                // [B,D]

    float *part, *pacc;
    float2* pmz;
    __nv_bfloat16 *actA, *WqB, *WkB, *WvB;
    cudaGetSymbolAddress((void**)&part, g_part);
    cudaGetSymbolAddress((void**)&pacc, g_pacc);
    cudaGetSymbolAddress((void**)&pmz,  g_pmz);
    cudaGetSymbolAddress((void**)&actA, g_actA);
    cudaGetSymbolAddress((void**)&WqB,  g_WqB);
    cudaGetSymbolAddress((void**)&WkB,  g_WkB);
    cudaGetSymbolAddress((void**)&WvB,  g_WvB);

    dim3 mgrid(8, 4, SPLITK);   // 128 CTAs per GEMM

    // all 4 conversions in ONE launch (jobs run concurrently)
    conv_all<<<1664, 256>>>(Wq, Wv, z, Wk, WqB, WvB, actA, WkB);

    // 1. q = z @ Wq^T + bq
    mma_gemm<<<mgrid, 256>>>(actA, WqB, part);
    reduce_conv<<<128, 256>>>(part, bq, actA);
    // 2. qk = q @ Wk  (partials consumed directly by attn_part)
    mma_gemm<<<mgrid, 256>>>(actA, WkB, part);
    // 3. fused scores + softmax + weighted-input accumulation
    attn_part<<<dim3(B_SZ, TSPLIT), 256>>>(x, part, pacc, pmz);
    attn_combine_conv<<<B_SZ, 256>>>(pacc, pmz, actA);
    // 4. out = ctxf @ Wv^T + bv
    mma_gemm<<<mgrid, 256>>>(actA, WvB, part);
    reduce_k<<<128, 256>>>(part, bv, out);
}

// round 15
// speedup vs baseline: 1.1007x; 1.0158x over previous
#include <cuda_runtime.h>
#include <cuda_bf16.h>
#include <math.h>
#include <stdint.h>

#define B_SZ 512
#define T_SZ 256
#define F_SZ 1024
#define KP   3072               // K' = 3*F (tri-concat bf16 split)
#define SPLITK 8
#define KSL  (KP / SPLITK)      // 384 per split slice
#define NSTAGE (KSL / 32)       // 12 stages of 32 bf16
#define SROW 40                 // smem row stride in bf16 (conflict-free)
#define TSPLIT 4
#define TCH (T_SZ / TSPLIT)     // 64
#define NIT (TCH / 8)           // 8

// Scratch (allocation-free rule: __device__ globals)
__device__ float  g_part[SPLITK * B_SZ * F_SZ];
__device__ float  g_pacc[TSPLIT * B_SZ * F_SZ];
__device__ float2 g_pmz[TSPLIT * B_SZ];
__device__ __nv_bfloat16 g_actA[B_SZ * KP];   // activation triple (z -> q -> ctxf)
__device__ __nv_bfloat16 g_WqB[F_SZ * KP];
__device__ __nv_bfloat16 g_WkB[F_SZ * KP];    // transposed Wk triple
__device__ __nv_bfloat16 g_WvB[F_SZ * KP];

// ===========================================================================
// bf16 split helpers
// ===========================================================================
__device__ __forceinline__ void split4(float4 v, uint2& hi, uint2& lo) {
    __nv_bfloat16 hx = __float2bfloat16_rn(v.x), hy = __float2bfloat16_rn(v.y);
    __nv_bfloat16 hz = __float2bfloat16_rn(v.z), hw = __float2bfloat16_rn(v.w);
    __nv_bfloat16 lx = __float2bfloat16_rn(v.x - __bfloat162float(hx));
    __nv_bfloat16 ly = __float2bfloat16_rn(v.y - __bfloat162float(hy));
    __nv_bfloat16 lz = __float2bfloat16_rn(v.z - __bfloat162float(hz));
    __nv_bfloat16 lw = __float2bfloat16_rn(v.w - __bfloat162float(hw));
    __nv_bfloat162 h0 = __nv_bfloat162(hx, hy), h1 = __nv_bfloat162(hz, hw);
    __nv_bfloat162 l0 = __nv_bfloat162(lx, ly), l1 = __nv_bfloat162(lz, lw);
    hi.x = *(unsigned*)&h0; hi.y = *(unsigned*)&h1;
    lo.x = *(unsigned*)&l0; lo.y = *(unsigned*)&l1;
}

// ===========================================================================
// ONE merged conversion kernel (4 independent jobs, block-range dispatch)
// ===========================================================================
__global__ __launch_bounds__(256) void conv_all(const float* __restrict__ Wq,
                                                const float* __restrict__ Wv,
                                                const float* __restrict__ z,
                                                const float* __restrict__ Wk,
                                                __nv_bfloat16* __restrict__ WqB,
                                                __nv_bfloat16* __restrict__ WvB,
                                                __nv_bfloat16* __restrict__ actA,
                                                __nv_bfloat16* __restrict__ WkB)
{
    const int bid = blockIdx.x;
    const int t = threadIdx.x;

    if (bid < 512) {                      // Wq or Wv, B-pattern [hi|hi|lo]
        const float* W = (bid < 256) ? Wq : Wv;
        __nv_bfloat16* out = (bid < 256) ? WqB : WvB;
        const int i0 = (bid & 255) * 1024 + t;
        #pragma unroll
        for (int u = 0; u < 4; u++) {
            int idx = i0 + u * 256;
            float4 v = ((const float4*)W)[idx];
            int row = idx >> 8, c = (idx & 255) * 4;
            uint2 hi, lo; split4(v, hi, lo);
            __nv_bfloat16* base = out + (size_t)row * KP + c;
            *(uint2*)(base)        = hi;
            *(uint2*)(base + 1024) = hi;
            *(uint2*)(base + 2048) = lo;
        }
    } else if (bid < 640) {               // z, A-pattern [hi|lo|hi]
        const int i0 = (bid - 512) * 1024 + t;
        #pragma unroll
        for (int u = 0; u < 4; u++) {
            int idx = i0 + u * 256;
            float4 v = ((const float4*)z)[idx];
            int row = idx >> 8, c = (idx & 255) * 4;
            uint2 hi, lo; split4(v, hi, lo);
            __nv_bfloat16* base = actA + (size_t)row * KP + c;
            *(uint2*)(base)        = hi;
            *(uint2*)(base + 1024) = lo;
            *(uint2*)(base + 2048) = hi;
        }
    } else {                              // Wk transpose + B-pattern
        __shared__ float tl[32][33];
        const int r = bid - 640;          // 0..1023
        const int f0 = (r & 31) * 32, d0 = (r >> 5) * 32;
        const int tx = t & 31, ty = t >> 5;    // 32 x 8
        #pragma unroll
        for (int i = 0; i < 32; i += 8)
            tl[ty + i][tx] = Wk[(size_t)(d0 + ty + i) * F_SZ + f0 + tx];
        __syncthreads();
        #pragma unroll
        for (int i = 0; i < 32; i += 8) {
            float v = tl[tx][ty + i];
            __nv_bfloat16 hi = __float2bfloat16_rn(v);
            __nv_bfloat16 lo = __float2bfloat16_rn(v - __bfloat162float(hi));
            __nv_bfloat16* base = WkB + (size_t)(f0 + ty + i) * KP + d0 + tx;
            base[0]    = hi;
            base[1024] = hi;
            base[2048] = lo;
        }
    }
}

// Reduce SPLITK partials + bias -> A-pattern bf16 triple. 4/thread. grid 128.
__global__ __launch_bounds__(256) void reduce_conv(const float* __restrict__ part,
                                                   const float* __restrict__ bias,
                                                   __nv_bfloat16* __restrict__ out)
{
    const int i0 = blockIdx.x * 1024 + threadIdx.x;
    const int Q = B_SZ * F_SZ / 4;
    const float4* p = (const float4*)part;
    #pragma unroll
    for (int u = 0; u < 4; u++) {
        int idx = i0 + u * 256;
        float4 s0 = p[idx], s1 = p[idx + Q];
        #pragma unroll
        for (int s = 2; s < SPLITK; s += 2) {
            float4 a = p[idx + s * Q], b = p[idx + (s + 1) * Q];
            s0.x += a.x; s0.y += a.y; s0.z += a.z; s0.w += a.w;
            s1.x += b.x; s1.y += b.y; s1.z += b.z; s1.w += b.w;
        }
        float4 bb = ((const float4*)bias)[idx & 255];
        float4 v;
        v.x = s0.x + s1.x + bb.x;
        v.y = s0.y + s1.y + bb.y;
        v.z = s0.z + s1.z + bb.z;
        v.w = s0.w + s1.w + bb.w;
        int row = idx >> 8, c = (idx & 255) * 4;
        uint2 hi, lo; split4(v, hi, lo);
        __nv_bfloat16* base = out + (size_t)row * KP + c;
        *(uint2*)(base)        = hi;
        *(uint2*)(base + 1024) = lo;
        *(uint2*)(base + 2048) = hi;
    }
}

// ===========================================================================
// bf16 HMMA GEMM. Grid (8, 4, SPLITK) = 256 CTAs -> single wave at occ 2.
// ===========================================================================
__device__ __forceinline__ void mma16816(float* c, const uint32_t* a, const uint32_t* b) {
    asm volatile(
        "mma.sync.aligned.m16n8k16.row.col.f32.bf16.bf16.f32 "
        "{%0,%1,%2,%3}, {%4,%5,%6,%7}, {%8,%9}, {%0,%1,%2,%3};"
        : "+f"(c[0]), "+f"(c[1]), "+f"(c[2]), "+f"(c[3])
        : "r"(a[0]), "r"(a[1]), "r"(a[2]), "r"(a[3]), "r"(b[0]), "r"(b[1]));
}

__global__ __launch_bounds__(256, 2) void mma_gemm(const __nv_bfloat16* __restrict__ Aq,
                                                   const __nv_bfloat16* __restrict__ Bq,
                                                   float* __restrict__ Cpart)
{
    __shared__ __align__(16) __nv_bfloat16 sA[2][128 * SROW];
    __shared__ __align__(16) __nv_bfloat16 sB[2][128 * SROW];

    const int bn = blockIdx.x * 128;
    const int bm = blockIdx.y * 128;
    const int s  = blockIdx.z;
    const int k0 = s * KSL;
    const int tid = threadIdx.x;
    const int wid = tid >> 5;
    const int l = tid & 31;
    const int wm = wid & 1;
    const int wn = wid >> 1;
    const int lq = l >> 2;
    const int lr = l & 3;

    const int row0 = tid >> 2,           kc0 = (tid & 3) * 8;
    const int row1 = (tid + 256) >> 2,   kc1 = (tid & 3) * 8;

    const __nv_bfloat16* Ag0 = Aq + (size_t)(bm + row0) * KP + k0 + kc0;
    const __nv_bfloat16* Ag1 = Aq + (size_t)(bm + row1) * KP + k0 + kc1;
    const __nv_bfloat16* Bg0 = Bq + (size_t)(bn + row0) * KP + k0 + kc0;
    const __nv_bfloat16* Bg1 = Bq + (size_t)(bn + row1) * KP + k0 + kc1;

    const int sa0 = row0 * SROW + kc0, sa1 = row1 * SROW + kc1;

    float acc[4][4][4];
    #pragma unroll
    for (int i = 0; i < 4; i++)
        #pragma unroll
        for (int j = 0; j < 4; j++)
            #pragma unroll
            for (int r = 0; r < 4; r++) acc[i][j][r] = 0.f;

    {
        uint4 a0 = *(const uint4*)Ag0, a1 = *(const uint4*)Ag1;
        uint4 b0 = *(const uint4*)Bg0, b1 = *(const uint4*)Bg1;
        *(uint4*)&sA[0][sa0] = a0; *(uint4*)&sA[0][sa1] = a1;
        *(uint4*)&sB[0][sa0] = b0; *(uint4*)&sB[0][sa1] = b1;
    }
    __syncthreads();

    int buf = 0;
    for (int st = 0; st < NSTAGE; st++) {
        uint4 pa0, pa1, pb0, pb1;
        if (st + 1 < NSTAGE) {
            pa0 = *(const uint4*)(Ag0 + (st + 1) * 32);
            pa1 = *(const uint4*)(Ag1 + (st + 1) * 32);
            pb0 = *(const uint4*)(Bg0 + (st + 1) * 32);
            pb1 = *(const uint4*)(Bg1 + (st + 1) * 32);
        }

        #pragma unroll
        for (int ks = 0; ks < 2; ks++) {
            const int kc = ks * 16 + lr * 2;
            uint32_t af[4][4];
            #pragma unroll
            for (int i = 0; i < 4; i++) {
                const __nv_bfloat16* base = &sA[buf][(wm * 64 + i * 16 + lq) * SROW + kc];
                af[i][0] = *(const uint32_t*)(base);
                af[i][1] = *(const uint32_t*)(base + 8 * SROW);
                af[i][2] = *(const uint32_t*)(base + 8);
                af[i][3] = *(const uint32_t*)(base + 8 * SROW + 8);
            }
            uint32_t bfr[4][2];
            #pragma unroll
            for (int j = 0; j < 4; j++) {
                const __nv_bfloat16* base = &sB[buf][(wn * 32 + j * 8 + lq) * SROW + kc];
                bfr[j][0] = *(const uint32_t*)(base);
                bfr[j][1] = *(const uint32_t*)(base + 8);
            }
            #pragma unroll
            for (int i = 0; i < 4; i++)
                #pragma unroll
                for (int j = 0; j < 4; j++)
                    mma16816(acc[i][j], af[i], bfr[j]);
        }

        if (st + 1 < NSTAGE) {
            int nb = buf ^ 1;
            *(uint4*)&sA[nb][sa0] = pa0; *(uint4*)&sA[nb][sa1] = pa1;
            *(uint4*)&sB[nb][sa0] = pb0; *(uint4*)&sB[nb][sa1] = pb1;
            __syncthreads();
            buf = nb;
        }
    }

    float* Cp = Cpart + (size_t)s * (B_SZ * F_SZ);
    #pragma unroll
    for (int i = 0; i < 4; i++) {
        #pragma unroll
        for (int j = 0; j < 4; j++) {
            int row = bm + wm * 64 + i * 16 + lq;
            int col = bn + wn * 32 + j * 8 + lr * 2;
            *(float2*)(Cp + (size_t)row * F_SZ + col) =
                make_float2(acc[i][j][0], acc[i][j][1]);
            *(float2*)(Cp + (size_t)(row + 8) * F_SZ + col) =
                make_float2(acc[i][j][2], acc[i][j][3]);
        }
    }
}

// ---------------------------------------------------------------------------
// Reduce SPLITK partials (+ bias) -> fp32 out. 4 float4/thread, grid 128.
// ---------------------------------------------------------------------------
__global__ __launch_bounds__(256) void reduce_k(const float* __restrict__ part,
                                                const float* __restrict__ bias,
                                                float* __restrict__ out)
{
    const int i0 = blockIdx.x * 1024 + threadIdx.x;
    const int Q = B_SZ * F_SZ / 4;
    const float4* p = (const float4*)part;
    #pragma unroll
    for (int u = 0; u < 4; u++) {
        int idx = i0 + u * 256;
        float4 s0 = p[idx], s1 = p[idx + Q];
        #pragma unroll
        for (int s = 2; s < SPLITK; s += 2) {
            float4 a = p[idx + s * Q], b = p[idx + (s + 1) * Q];
            s0.x += a.x; s0.y += a.y; s0.z += a.z; s0.w += a.w;
            s1.x += b.x; s1.y += b.y; s1.z += b.z; s1.w += b.w;
        }
        float4 bb = ((const float4*)bias)[idx & 255];
        float4 o;
        o.x = s0.x + s1.x + bb.x;
        o.y = s0.y + s1.y + bb.y;
        o.z = s0.z + s1.z + bb.z;
        o.w = s0.w + s1.w + bb.w;
        ((float4*)out)[idx] = o;
    }
}

// ---------------------------------------------------------------------------
// Attention partial (R10 + L2 prefetch, proven ~77us). grid (B, TSPLIT).
// ---------------------------------------------------------------------------
__global__ __launch_bounds__(256, 2) void attn_part(const float* __restrict__ x,
                                                    const float* __restrict__ qkpart,
                                                    float* __restrict__ pacc,
                                                    float2* __restrict__ pmz)
{
    const int b = blockIdx.x;
    const int h = blockIdx.y;
    const int tid = threadIdx.x;
    const int w = tid >> 5;
    const int l = tid & 31;

    __shared__ float red[8][256];
    __shared__ float s_tile[8];

    float4 qk;
    {
        const int Q = B_SZ * F_SZ / 4;
        const int idx = b * 256 + tid;
        const float4* p = (const float4*)qkpart;
        float4 s0 = p[idx], s1 = p[idx + Q];
        #pragma unroll
        for (int s = 2; s < SPLITK; s += 2) {
            float4 a = p[idx + s * Q], bb = p[idx + (s + 1) * Q];
            s0.x += a.x; s0.y += a.y; s0.z += a.z; s0.w += a.w;
            s1.x += bb.x; s1.y += bb.y; s1.z += bb.z; s1.w += bb.w;
        }
        qk = make_float4(s0.x + s1.x, s0.y + s1.y, s0.z + s1.z, s0.w + s1.w);
    }

    const float4* x4 = (const float4*)(x + (size_t)b * T_SZ * F_SZ
                                         + (size_t)h * TCH * F_SZ);
    float4 cur[8], nxt[8];
    #pragma unroll
    for (int i = 0; i < 8; i++) cur[i] = x4[(size_t)i * 256 + tid];
    #pragma unroll
    for (int i = 0; i < 8; i++)   // L2 prefetch of tile 1
        asm volatile("prefetch.global.L2 [%0];"
                     :: "l"(x4 + (size_t)(8 + i) * 256 + tid));

    float m = -INFINITY, Z = 0.0f;
    float4 acc = make_float4(0.f, 0.f, 0.f, 0.f);

    #pragma unroll
    for (int it = 0; it < NIT; it++) {
        if (it + 1 < NIT) {
            #pragma unroll
            for (int i = 0; i < 8; i++)
                nxt[i] = x4[(size_t)((it + 1) * 8 + i) * 256 + tid];
        }
        if (it + 2 < NIT) {           // DRAM->L2 prefetch two tiles ahead
            #pragma unroll
            for (int i = 0; i < 8; i++)
                asm volatile("prefetch.global.L2 [%0];"
                             :: "l"(x4 + (size_t)((it + 2) * 8 + i) * 256 + tid));
        }

        #pragma unroll
        for (int i = 0; i < 8; i++) {
            float4 xv = cur[i];
            red[i][tid] = xv.x * qk.x + xv.y * qk.y + xv.z * qk.z + xv.w * qk.w;
        }
        __syncthreads();
        {
            float s = 0.f;
            #pragma unroll
            for (int j = 0; j < 8; j++) s += red[w][l + 32 * j];
            #pragma unroll
            for (int off = 16; off; off >>= 1)
                s += __shfl_down_sync(0xffffffffu, s, off);
            if (l == 0) s_tile[w] = s;
        }
        __syncthreads();

        float tm = s_tile[0];
        #pragma unroll
        for (int t = 1; t < 8; t++) tm = fmaxf(tm, s_tile[t]);
        float m_new = fmaxf(m, tm);
        float scale = __expf(m - m_new);
        Z *= scale;
        acc.x *= scale; acc.y *= scale; acc.z *= scale; acc.w *= scale;
        #pragma unroll
        for (int t = 0; t < 8; t++) {
            float wt = __expf(s_tile[t] - m_new);
            Z += wt;
            float4 xv = cur[t];
            acc.x += wt * xv.x; acc.y += wt * xv.y;
            acc.z += wt * xv.z; acc.w += wt * xv.w;
        }
        m = m_new;
        if (it + 1 < NIT) {
            #pragma unroll
            for (int i = 0; i < 8; i++) cur[i] = nxt[i];
        }
    }

    ((float4*)pacc)[(size_t)(b * TSPLIT + h) * 256 + tid] = acc;
    if (tid == 0) pmz[b * TSPLIT + h] = make_float2(m, Z);
}

// ---------------------------------------------------------------------------
// Combine T-chunks, normalize, convert to bf16 A-pattern triple for GEMM3.
// ---------------------------------------------------------------------------
__global__ __launch_bounds__(256) void attn_combine_conv(const float* __restrict__ pacc,
                                                         const float2* __restrict__ pmz,
                                                         __nv_bfloat16* __restrict__ out)
{
    const int b = blockIdx.x;
    const int tid = threadIdx.x;

    float2 mz[TSPLIT];
    #pragma unroll
    for (int i = 0; i < TSPLIT; i++) mz[i] = pmz[TSPLIT * b + i];
    float m = mz[0].x;
    #pragma unroll
    for (int i = 1; i < TSPLIT; i++) m = fmaxf(m, mz[i].x);
    float sc[TSPLIT], Z = 0.f;
    #pragma unroll
    for (int i = 0; i < TSPLIT; i++) { sc[i] = __expf(mz[i].x - m); Z += mz[i].y * sc[i]; }
    float inv = 1.0f / Z;

    float4 o = make_float4(0.f, 0.f, 0.f, 0.f);
    #pragma unroll
    for (int i = 0; i < TSPLIT; i++) {
        float4 a = ((const float4*)pacc)[(size_t)(TSPLIT * b + i) * 256 + tid];
        o.x += a.x * sc[i]; o.y += a.y * sc[i];
        o.z += a.z * sc[i]; o.w += a.w * sc[i];
    }
    o.x *= inv; o.y *= inv; o.z *= inv; o.w *= inv;

    uint2 hi, lo; split4(o, hi, lo);
    __nv_bfloat16* base = out + (size_t)b * KP + tid * 4;
    *(uint2*)(base)        = hi;
    *(uint2*)(base + 1024) = lo;
    *(uint2*)(base + 2048) = hi;
}

// ---------------------------------------------------------------------------
extern "C" void kernel_launch(void* const* d_in, const int* in_sizes, int n_in,
                              void* d_out, int out_size)
{
    const float* z  = (const float*)d_in[0];   // [B,F]
    const float* x  = (const float*)d_in[1];   // [B,T,F]
    const float* Wq = (const float*)d_in[2];   // [D,F]
    const float* Wk = (const float*)d_in[3];   // [D,F]
    const float* Wv = (const float*)d_in[4];   // [D,F]
    const float* bq = (const float*)d_in[5];   // [D]
    // d_in[6] = bk: softmax-invariant -> dropped
    const float* bv = (const float*)d_in[7];   // [D]
    float* out = (float*)d_out;                // [B,D]

    float *part, *pacc;
    float2* pmz;
    __nv_bfloat16 *actA, *WqB, *WkB, *WvB;
    cudaGetSymbolAddress((void**)&part, g_part);
    cudaGetSymbolAddress((void**)&pacc, g_pacc);
    cudaGetSymbolAddress((void**)&pmz,  g_pmz);
    cudaGetSymbolAddress((void**)&actA, g_actA);
    cudaGetSymbolAddress((void**)&WqB,  g_WqB);
    cudaGetSymbolAddress((void**)&WkB,  g_WkB);
    cudaGetSymbolAddress((void**)&WvB,  g_WvB);

    dim3 mgrid(8, 4, SPLITK);   // 256 CTAs per GEMM -> single wave at occ 2

    // all 4 conversions in ONE launch (jobs run concurrently)
    conv_all<<<1664, 256>>>(Wq, Wv, z, Wk, WqB, WvB, actA, WkB);

    // 1. q = z @ Wq^T + bq
    mma_gemm<<<mgrid, 256>>>(actA, WqB, part);
    reduce_conv<<<128, 256>>>(part, bq, actA);
    // 2. qk = q @ Wk  (partials consumed directly by attn_part)
    mma_gemm<<<mgrid, 256>>>(actA, WkB, part);
    // 3. fused scores + softmax + weighted-input accumulation
    attn_part<<<dim3(B_SZ, TSPLIT), 256>>>(x, part, pacc, pmz);
    attn_combine_conv<<<B_SZ, 256>>>(pacc, pmz, actA);
    // 4. out = ctxf @ Wv^T + bv
    mma_gemm<<<mgrid, 256>>>(actA, WvB, part);
    reduce_k<<<128, 256>>>(part, bv, out);
}